// round 7
// baseline (speedup 1.0000x reference)
#include <cuda_runtime.h>
#include <cuda_bf16.h>

// Problem constants
#define TT   64
#define WW   88
#define HPc  48
#define CIN  53
#define HLc  12
#define G4   48
#define NHh  4
#define HDd  6
#define NUc  24
#define KK   25
#define NPX  (TT*WW)   // 5632
#define PITCH 26       // float2-aligned; conflict-free

// Scratch buffers (device globals)
__device__ float g_pre0[WW*TT*96];   // layer-0 pregates [w][t][96]
__device__ float g_q0[NPX*NUc];
__device__ float g_k0[NPX*NUc];
__device__ float g_v0[NPX*NUc];
__device__ float g_q1[NPX*NUc];
__device__ float g_k1[NPX*NUc];
__device__ float g_v1[NPX*NUc];

#define QSCALE 0.4082482904638631f

__device__ __forceinline__ float sigf(float x) {
    return __fdividef(1.0f, 1.0f + __expf(-x));
}
__device__ __forceinline__ float tanh_fast(float x) {
    return fmaf(2.0f, __fdividef(1.0f, 1.0f + __expf(-2.0f*x)), -1.0f);
}

// ---------------------------------------------------------------------------
// Layer-0 pregates for ALL (w,t): chip-filling. 176 blocks x 256.
// warp = gate-octet (8 warps x 12 gates = 96), lane = (w,t) pair.
// ---------------------------------------------------------------------------
__global__ void __launch_bounds__(256)
pre0_kernel(const float* __restrict__ features,   // (1,64,48,88)
            const int*   __restrict__ condition,  // (1,64,88)
            const float* __restrict__ mask,       // (1,64,88)
            const float* __restrict__ emb,        // (5,4)
            const float* __restrict__ wih0,       // (2,48,53) = 96 rows
            const float* __restrict__ bih0,       // (96,)
            const float* __restrict__ bhh0)       // (96,)
{
    __shared__ float wsh[96*CIN];   // 20.4 KB
    __shared__ float bsh[96];
    __shared__ float esh[20];
    const int tid = threadIdx.x;
    for (int x = tid; x < 96*CIN; x += 256) wsh[x] = wih0[x];
    if (tid < 96) bsh[tid] = bih0[tid] + bhh0[tid];
    if (tid < 20) esh[tid] = emb[tid];
    __syncthreads();

    const int lane = tid & 31, warp = tid >> 5;   // warp = octet (uniform)
    const int wt = blockIdx.x*32 + lane;          // 176*32 = 5632 exactly
    const int t = wt / WW, w = wt % WW;
    const int g0 = warp * 12;

    float acc[12];
    #pragma unroll
    for (int g = 0; g < 12; g++) acc[g] = bsh[g0 + g];

    // features (coalesced across lanes for fixed t,c)
    for (int c = 0; c < HPc; c++) {
        float x = __ldg(features + (t*HPc + c)*WW + w);
        #pragma unroll
        for (int g = 0; g < 12; g++)
            acc[g] = fmaf(x, wsh[(g0 + g)*CIN + c], acc[g]);
    }
    // embedding
    const int cd = __ldg(condition + t*WW + w);
    #pragma unroll
    for (int c2 = 0; c2 < 4; c2++) {
        float x = esh[cd*4 + c2];
        #pragma unroll
        for (int g = 0; g < 12; g++)
            acc[g] = fmaf(x, wsh[(g0 + g)*CIN + HPc + c2], acc[g]);
    }
    // mask
    {
        float x = __ldg(mask + t*WW + w);
        #pragma unroll
        for (int g = 0; g < 12; g++)
            acc[g] = fmaf(x, wsh[(g0 + g)*CIN + 52], acc[g]);
    }

    float* dst = g_pre0 + (w*TT + t)*96 + g0;
    #pragma unroll
    for (int g = 0; g < 12; g++) dst[g] = acc[g];
}

// ---------------------------------------------------------------------------
// Per-sequence: rec L0 -> pregate L1 -> rec L1 -> QKV(layer1). 88 x 384.
// ---------------------------------------------------------------------------
__global__ void __launch_bounds__(384)
lstm_rec_kernel(const float* __restrict__ whh0,
                const float* __restrict__ wih1, const float* __restrict__ whh1,
                const float* __restrict__ bih1, const float* __restrict__ bhh1,
                const float* __restrict__ qkv_w,  // (72,24)
                const float* __restrict__ qkv_b)  // (72,)
{
    const int w   = blockIdx.x;
    const int tid = threadIdx.x;

    __shared__ float pre [TT][96];
    __shared__ float hbuf[TT][2*HLc];

    // stage layer-0 pregates (coalesced float4)
    {
        const float4* src = (const float4*)(g_pre0 + w*TT*96);
        float4* dst = (float4*)&pre[0][0];
        for (int x = tid; x < TT*96/4; x += 384) dst[x] = src[x];
    }
    __syncthreads();

    // ---- layer-0 recurrence (2 warps, shfl) ----
    if (tid < 64) {
        const int dir = tid >> 5, u = tid & 31;
        float wi[HLc], wf[HLc], wg[HLc], wo[HLc];
        if (u < HLc) {
            #pragma unroll
            for (int c = 0; c < HLc; c++) {
                wi[c] = whh0[(dir*G4      + u)*HLc + c];
                wf[c] = whh0[(dir*G4 + 12 + u)*HLc + c];
                wg[c] = whh0[(dir*G4 + 24 + u)*HLc + c];
                wo[c] = whh0[(dir*G4 + 36 + u)*HLc + c];
            }
        } else {
            #pragma unroll
            for (int c = 0; c < HLc; c++) { wi[c]=wf[c]=wg[c]=wo[c]=0.f; }
        }
        float h = 0.f, cs = 0.f;
        for (int s = 0; s < TT; s++) {
            const int t = dir ? (TT - 1 - s) : s;
            float gi, gf, gg, go;
            if (u < HLc) {
                gi = pre[t][dir*G4      + u];
                gf = pre[t][dir*G4 + 12 + u];
                gg = pre[t][dir*G4 + 24 + u];
                go = pre[t][dir*G4 + 36 + u];
            } else { gi = gf = gg = go = 0.f; }
            #pragma unroll
            for (int c = 0; c < HLc; c++) {
                float hc = __shfl_sync(0xffffffffu, h, c);
                gi = fmaf(hc, wi[c], gi);
                gf = fmaf(hc, wf[c], gf);
                gg = fmaf(hc, wg[c], gg);
                go = fmaf(hc, wo[c], go);
            }
            cs = sigf(gf)*cs + sigf(gi)*tanh_fast(gg);
            h  = sigf(go)*tanh_fast(cs);
            if (u < HLc) hbuf[t][dir*HLc + u] = h;
        }
    }
    __syncthreads();

    // ---- layer-1 pregates: 384 = 4 t-chunks x 96 gates ----
    {
        const int gate = tid % 96;
        const int tq   = tid / 96;
        const int dir = gate / G4, g = gate % G4;
        float wr[2*HLc];
        const float* wrow = wih1 + (dir*G4 + g)*(2*HLc);
        #pragma unroll
        for (int c = 0; c < 2*HLc; c++) wr[c] = wrow[c];
        const float b = bih1[dir*G4 + g] + bhh1[dir*G4 + g];
        for (int t = tq*16; t < tq*16 + 16; t++) {
            float a0 = b, a1 = 0.f, a2 = 0.f, a3 = 0.f;
            #pragma unroll
            for (int c = 0; c < 2*HLc; c += 4) {
                a0 = fmaf(hbuf[t][c+0], wr[c+0], a0);
                a1 = fmaf(hbuf[t][c+1], wr[c+1], a1);
                a2 = fmaf(hbuf[t][c+2], wr[c+2], a2);
                a3 = fmaf(hbuf[t][c+3], wr[c+3], a3);
            }
            pre[t][gate] = (a0 + a1) + (a2 + a3);
        }
    }
    __syncthreads();

    // ---- layer-1 recurrence ----
    if (tid < 64) {
        const int dir = tid >> 5, u = tid & 31;
        float wi[HLc], wf[HLc], wg[HLc], wo[HLc];
        if (u < HLc) {
            #pragma unroll
            for (int c = 0; c < HLc; c++) {
                wi[c] = whh1[(dir*G4      + u)*HLc + c];
                wf[c] = whh1[(dir*G4 + 12 + u)*HLc + c];
                wg[c] = whh1[(dir*G4 + 24 + u)*HLc + c];
                wo[c] = whh1[(dir*G4 + 36 + u)*HLc + c];
            }
        } else {
            #pragma unroll
            for (int c = 0; c < HLc; c++) { wi[c]=wf[c]=wg[c]=wo[c]=0.f; }
        }
        float h = 0.f, cs = 0.f;
        for (int s = 0; s < TT; s++) {
            const int t = dir ? (TT - 1 - s) : s;
            float gi, gf, gg, go;
            if (u < HLc) {
                gi = pre[t][dir*G4      + u];
                gf = pre[t][dir*G4 + 12 + u];
                gg = pre[t][dir*G4 + 24 + u];
                go = pre[t][dir*G4 + 36 + u];
            } else { gi = gf = gg = go = 0.f; }
            #pragma unroll
            for (int c = 0; c < HLc; c++) {
                float hc = __shfl_sync(0xffffffffu, h, c);
                gi = fmaf(hc, wi[c], gi);
                gf = fmaf(hc, wf[c], gf);
                gg = fmaf(hc, wg[c], gg);
                go = fmaf(hc, wo[c], go);
            }
            cs = sigf(gf)*cs + sigf(gi)*tanh_fast(gg);
            h  = sigf(go)*tanh_fast(cs);
            if (u < HLc) hbuf[t][dir*HLc + u] = h;
        }
    }
    __syncthreads();

    // ---- fused QKV for layer 1: (t-chunk 0..3, oc 0..71) ----
    if (tid < 288) {
        const int oc = tid % 72;
        const int tq = tid / 72;
        float wr[NUc];
        const float* wrow = qkv_w + oc*NUc;
        #pragma unroll
        for (int c = 0; c < NUc; c++) wr[c] = wrow[c];
        const float b = qkv_b[oc];
        const int e  = oc / NUc;
        const int ch = oc % NUc;
        const float scale = (e == 0) ? QSCALE : 1.0f;
        float* dst = (e == 0) ? g_q0 : (e == 1) ? g_k0 : g_v0;
        for (int t = tq*16; t < tq*16 + 16; t++) {
            float a0 = b, a1 = 0.f, a2 = 0.f, a3 = 0.f;
            #pragma unroll
            for (int c = 0; c < NUc; c += 4) {
                a0 = fmaf(hbuf[t][c+0], wr[c+0], a0);
                a1 = fmaf(hbuf[t][c+1], wr[c+1], a1);
                a2 = fmaf(hbuf[t][c+2], wr[c+2], a2);
                a3 = fmaf(hbuf[t][c+3], wr[c+3], a3);
            }
            dst[(t*WW + w)*NUc + ch] = ((a0 + a1) + (a2 + a3)) * scale;
        }
    }
}

// ---------------------------------------------------------------------------
// NATTEN-2D: 2x8 pixel tile (16 px/block, 352 blocks). rpb staged in smem.
// Single pass, unshifted softmax. mode0 -> QKV layer2, mode1 -> final head.
// ---------------------------------------------------------------------------
__global__ void __launch_bounds__(1024)
natten_kernel(const float* __restrict__ qsrc,
              const float* __restrict__ ksrc,
              const float* __restrict__ vsrc,
              const float* __restrict__ rpb,    // (4,49,49)
              const float* __restrict__ pw,     // (24,24)
              const float* __restrict__ pb,     // (24,)
              const float* __restrict__ qkv_w,  // (72,24)  mode 0
              const float* __restrict__ qkv_b,  // (72,)    mode 0
              const float* __restrict__ ow,     // (5,24)   mode 1
              const float* __restrict__ ob,     // (5,)     mode 1
              float* __restrict__ out,
              int mode)
{
    const int i0 = blockIdx.y * 2;
    const int j0 = blockIdx.x * 8;
    extern __shared__ float sm[];
    float* ks   = sm;                           // [26*32][PITCH]
    float* vs   = ks + 26*32*PITCH;
    float* rpsh = vs + 26*32*PITCH;             // [4][26][32]
    float* ao   = rpsh + 4*26*32;               // [16][24]
    float* po   = ao + 16*NUc;                  // [16][24]
    float* wsh  = po + 16*NUc;                  // [72*24]
    float* bsh  = wsh + 72*NUc;                 // [72]

    const int tid = threadIdx.x;

    const int si0 = min(max(i0     - 12, 0), TT - KK);
    const int si1 = min(max(i0 + 1 - 12, 0), TT - KK);
    const int nrows = si1 + KK - si0;                       // 25 or 26
    const int sj_min  = min(max(j0     - 12, 0), WW - KK);
    const int sj_last = min(max(j0 + 7 - 12, 0), WW - KK);
    const int ncols   = sj_last + KK - sj_min;              // <= 32

    // rpb window bounds (monotone: rmin from row i0+1, cmin from col j0+7)
    const int rmin = si1 - (i0 + 1) + (KK - 1);
    const int cmin = sj_last - (j0 + 7) + (KK - 1);

    if (mode == 0) {
        for (int x = tid; x < 72*NUc; x += 1024) wsh[x] = qkv_w[x];
        if (tid < 72) bsh[tid] = qkv_b[tid];
    }

    // stage rpb sub-windows (4 heads x 26 x 32)
    for (int idx = tid; idx < 4*26*32; idx += 1024) {
        int n = idx / (26*32);
        int rem = idx - n*(26*32);
        int rr = rem >> 5, cc = rem & 31;
        int rrow = rmin + rr, rcol = cmin + cc;
        rpsh[idx] = (rrow < 49 && rcol < 49)
                    ? __ldg(rpb + n*2401 + rrow*49 + rcol) : 0.f;
    }

    // stage K/V window
    const int npx = nrows * ncols;
    for (int spx = tid; spx < npx; spx += 1024) {
        int a = spx / ncols, c = spx - a*ncols;
        int gpx = (si0 + a)*WW + (sj_min + c);
        float* kdst = ks + (a*32 + c)*PITCH;
        float* vdst = vs + (a*32 + c)*PITCH;
        const float4* kp = (const float4*)(ksrc + gpx*NUc);
        const float4* vp = (const float4*)(vsrc + gpx*NUc);
        #pragma unroll
        for (int f = 0; f < 6; f++) {
            float4 kd = kp[f];
            *(float2*)(kdst + f*4)     = make_float2(kd.x, kd.y);
            *(float2*)(kdst + f*4 + 2) = make_float2(kd.z, kd.w);
        }
        #pragma unroll
        for (int f = 0; f < 6; f++) {
            float4 vd = vp[f];
            *(float2*)(vdst + f*4)     = make_float2(vd.x, vd.y);
            *(float2*)(vdst + f*4 + 2) = make_float2(vd.z, vd.w);
        }
    }
    __syncthreads();

    const int warp = tid >> 5, lane = tid & 31;
    const int p = warp >> 2;           // column 0..7
    const int n = warp & 3;            // head
    const int j = j0 + p;
    const int sj = min(max(j - 12, 0), WW - KK);
    const int colbase = sj - sj_min;
    const int rc = (sj - j + (KK - 1)) - cmin;

    #pragma unroll
    for (int r = 0; r < 2; r++) {
        const int i = i0 + r;
        const int sir = (r == 0) ? si0 : si1;
        const int arow0 = sir - si0;                    // 0 or 1
        const int ra = (sir - i + (KK - 1)) - rmin;     // 0 or 1
        const int rpbase = n*(26*32) + ra*32 + rc;

        float qr[HDd];
        {
            const float* qp = qsrc + ((i*WW + j)*NUc + n*HDd);
            #pragma unroll
            for (int d = 0; d < HDd; d++) qr[d] = qp[d];
        }

        float sum = 0.f;
        float oacc[HDd] = {0.f,0.f,0.f,0.f,0.f,0.f};
        #pragma unroll
        for (int e0 = 0; e0 < 20; e0++) {
            int e = lane + e0*32;
            if (e < KK*KK) {
                int a = e / KK, c = e - a*KK;
                const int base = ((arow0 + a)*32 + colbase + c)*PITCH + n*HDd;
                const float* kp = ks + base;
                float2 k01 = *(const float2*)(kp);
                float2 k23 = *(const float2*)(kp + 2);
                float2 k45 = *(const float2*)(kp + 4);
                float lg = rpsh[rpbase + a*32 + c];
                lg = fmaf(qr[0], k01.x, lg);
                lg = fmaf(qr[1], k01.y, lg);
                lg = fmaf(qr[2], k23.x, lg);
                lg = fmaf(qr[3], k23.y, lg);
                lg = fmaf(qr[4], k45.x, lg);
                lg = fmaf(qr[5], k45.y, lg);
                float pr = __expf(lg);
                sum += pr;
                const float* vp = vs + base;
                float2 v01 = *(const float2*)(vp);
                float2 v23 = *(const float2*)(vp + 2);
                float2 v45 = *(const float2*)(vp + 4);
                oacc[0] = fmaf(pr, v01.x, oacc[0]);
                oacc[1] = fmaf(pr, v01.y, oacc[1]);
                oacc[2] = fmaf(pr, v23.x, oacc[2]);
                oacc[3] = fmaf(pr, v23.y, oacc[3]);
                oacc[4] = fmaf(pr, v45.x, oacc[4]);
                oacc[5] = fmaf(pr, v45.y, oacc[5]);
            }
        }
        #pragma unroll
        for (int o = 16; o > 0; o >>= 1) {
            sum += __shfl_xor_sync(0xffffffffu, sum, o);
            #pragma unroll
            for (int d = 0; d < HDd; d++)
                oacc[d] += __shfl_xor_sync(0xffffffffu, oacc[d], o);
        }
        if (lane == 0) {
            float inv = 1.0f / sum;
            #pragma unroll
            for (int d = 0; d < HDd; d++)
                ao[(r*8 + p)*NUc + n*HDd + d] = oacc[d]*inv;
        }
    }
    __syncthreads();

    // output projection (24x24) for 16 pixels
    if (tid < 16*NUc) {
        int pp = tid / NUc, oc = tid % NUc;
        float acc = __ldg(pb + oc);
        const float* wrow = pw + oc*NUc;
        #pragma unroll
        for (int ic = 0; ic < NUc; ic++)
            acc = fmaf(ao[pp*NUc + ic], __ldg(wrow + ic), acc);
        po[pp*NUc + oc] = acc;
    }
    __syncthreads();

    if (mode == 0) {
        // fused QKV for layer 2: 16 px * 72 oc = 1152 tasks
        for (int idx = tid; idx < 16*72; idx += 1024) {
            int pp = idx / 72, oc = idx % 72;
            float acc = bsh[oc];
            const float* wrow = wsh + oc*NUc;
            const float* xr = po + pp*NUc;
            #pragma unroll
            for (int c = 0; c < NUc; c++) acc = fmaf(xr[c], wrow[c], acc);
            int e = oc / NUc, ch = oc % NUc;
            int gpx = (i0 + (pp >> 3))*WW + j0 + (pp & 7);
            if      (e == 0) g_q1[gpx*NUc + ch] = acc * QSCALE;
            else if (e == 1) g_k1[gpx*NUc + ch] = acc;
            else             g_v1[gpx*NUc + ch] = acc;
        }
    } else {
        // final head (24 -> 5)
        if (tid < 16*5) {
            int pp = tid / 5, rr = tid % 5;
            float acc = __ldg(ob + rr);
            const float* wrow = ow + rr*NUc;
            #pragma unroll
            for (int ic = 0; ic < NUc; ic++)
                acc = fmaf(po[pp*NUc + ic], __ldg(wrow + ic), acc);
            out[((i0 + (pp >> 3))*WW + j0 + (pp & 7))*5 + rr] = acc;
        }
    }
}

// ---------------------------------------------------------------------------
extern "C" void kernel_launch(void* const* d_in, const int* in_sizes, int n_in,
                              void* d_out, int out_size)
{
    const float* features  = (const float*)d_in[0];
    const int*   condition = (const int*)  d_in[1];
    const float* mask      = (const float*)d_in[2];
    const float* emb       = (const float*)d_in[3];
    const float* wih0      = (const float*)d_in[4];
    const float* whh0      = (const float*)d_in[5];
    const float* bih0      = (const float*)d_in[6];
    const float* bhh0      = (const float*)d_in[7];
    const float* wih1      = (const float*)d_in[8];
    const float* whh1      = (const float*)d_in[9];
    const float* bih1      = (const float*)d_in[10];
    const float* bhh1      = (const float*)d_in[11];
    const float* qkv_w     = (const float*)d_in[12];
    const float* qkv_b     = (const float*)d_in[13];
    const float* rpb       = (const float*)d_in[14];
    const float* proj_w    = (const float*)d_in[15];
    const float* proj_b    = (const float*)d_in[16];
    const float* out_w     = (const float*)d_in[17];
    const float* out_b     = (const float*)d_in[18];
    float* out = (float*)d_out;

    float *pq0, *pk0, *pv0, *pq1, *pk1, *pv1;
    cudaGetSymbolAddress((void**)&pq0, g_q0);
    cudaGetSymbolAddress((void**)&pk0, g_k0);
    cudaGetSymbolAddress((void**)&pv0, g_v0);
    cudaGetSymbolAddress((void**)&pq1, g_q1);
    cudaGetSymbolAddress((void**)&pk1, g_k1);
    cudaGetSymbolAddress((void**)&pv1, g_v1);

    const int natten_smem =
        (2*26*32*PITCH + 4*26*32 + 2*16*NUc + 72*NUc + 72) * (int)sizeof(float);
    cudaFuncSetAttribute(natten_kernel,
                         cudaFuncAttributeMaxDynamicSharedMemorySize, natten_smem);

    // 1) layer-0 pregates (chip-filling)
    pre0_kernel<<<176, 256>>>(features, condition, mask, emb,
                              wih0, bih0, bhh0);

    // 2) recurrences + layer-1 + QKV(layer1), per sequence
    lstm_rec_kernel<<<WW, 384>>>(whh0, wih1, whh1, bih1, bhh1, qkv_w, qkv_b);

    dim3 ngrid(WW/8, TT/2);

    // 3) NATTEN layer 1 (+ fused QKV for layer 2)
    natten_kernel<<<ngrid, 1024, natten_smem>>>(pq0, pk0, pv0,
                                                rpb, proj_w, proj_b,
                                                qkv_w, qkv_b, out_w, out_b,
                                                nullptr, 0);

    // 4) NATTEN layer 2 (+ fused head) -> d_out
    natten_kernel<<<ngrid, 1024, natten_smem>>>(pq1, pk1, pv1,
                                                rpb, proj_w, proj_b,
                                                qkv_w, qkv_b, out_w, out_b,
                                                out, 1);
}

// round 8
// speedup vs baseline: 1.3718x; 1.3718x over previous
#include <cuda_runtime.h>
#include <cuda_bf16.h>

// Problem constants
#define TT   64
#define WW   88
#define HPc  48
#define CIN  53
#define HLc  12
#define G4   48
#define NHh  4
#define HDd  6
#define NUc  24
#define KK   25
#define NPX  (TT*WW)   // 5632
#define PITCH 26       // float2-aligned; conflict-free per 16-lane phase
#define UROWS 28       // max union rows for a 4-row tile
#define RPROWS 28

// Scratch buffers (device globals)
__device__ float g_q0[NPX*NUc];
__device__ float g_k0[NPX*NUc];
__device__ float g_v0[NPX*NUc];
__device__ float g_q1[NPX*NUc];
__device__ float g_k1[NPX*NUc];
__device__ float g_v1[NPX*NUc];

#define QSCALE 0.4082482904638631f

__device__ __forceinline__ float sigf(float x) {
    return __fdividef(1.0f, 1.0f + __expf(-x));
}
__device__ __forceinline__ float tanh_fast(float x) {
    return fmaf(2.0f, __fdividef(1.0f, 1.0f + __expf(-2.0f*x)), -1.0f);
}

// ---------------------------------------------------------------------------
// Fused LSTM (R6 structure) + all weights staged in smem.
// Block per sequence (w), 384 threads.
// ---------------------------------------------------------------------------
__global__ void __launch_bounds__(384)
lstm_kernel(const float* __restrict__ features,
            const int*   __restrict__ condition,
            const float* __restrict__ mask,
            const float* __restrict__ emb,
            const float* __restrict__ wih0, const float* __restrict__ whh0,
            const float* __restrict__ bih0, const float* __restrict__ bhh0,
            const float* __restrict__ wih1, const float* __restrict__ whh1,
            const float* __restrict__ bih1, const float* __restrict__ bhh1,
            const float* __restrict__ qkv_w,
            const float* __restrict__ qkv_b)
{
    const int w   = blockIdx.x;
    const int tid = threadIdx.x;

    __shared__ float xs  [TT][CIN];
    __shared__ float pre [TT][96];
    __shared__ float hbuf[TT][2*HLc];
    __shared__ float w0sh [96*CIN];
    __shared__ float wh0sh[96*HLc];
    __shared__ float w1sh [96*2*HLc];
    __shared__ float wh1sh[96*HLc];
    __shared__ float wqsh [72*NUc];
    __shared__ float b0sh[96], b1sh[96], bqsh[72];

    // ---- cooperative staging: inputs + ALL weights ----
    for (int idx = tid; idx < TT*CIN; idx += 384) {
        int t = idx / CIN, c = idx % CIN;
        float val;
        if (c < HPc)            val = features[(t*HPc + c)*WW + w];
        else if (c < HPc + 4)   val = emb[condition[t*WW + w]*4 + (c - HPc)];
        else                    val = mask[t*WW + w];
        xs[t][c] = val;
    }
    for (int x = tid; x < 96*CIN;   x += 384) w0sh[x]  = wih0[x];
    for (int x = tid; x < 96*HLc;   x += 384) wh0sh[x] = whh0[x];
    for (int x = tid; x < 96*2*HLc; x += 384) w1sh[x]  = wih1[x];
    for (int x = tid; x < 96*HLc;   x += 384) wh1sh[x] = whh1[x];
    for (int x = tid; x < 72*NUc;   x += 384) wqsh[x]  = qkv_w[x];
    if (tid < 96) b0sh[tid] = bih0[tid] + bhh0[tid];
    if (tid < 96) b1sh[tid] = bih1[tid] + bhh1[tid];
    if (tid < 72) bqsh[tid] = qkv_b[tid];
    __syncthreads();

    // ---- layer-0 pregates: 4 t-chunks x 96 gates ----
    {
        const int gate = tid % 96;
        const int tq   = tid / 96;
        float wr[CIN];
        #pragma unroll
        for (int c = 0; c < CIN; c++) wr[c] = w0sh[gate*CIN + c];
        const float b = b0sh[gate];
        for (int t = tq*16; t < tq*16 + 16; t++) {
            float a0 = b, a1 = 0.f, a2 = 0.f, a3 = 0.f;
            #pragma unroll
            for (int c = 0; c < 52; c += 4) {
                a0 = fmaf(xs[t][c+0], wr[c+0], a0);
                a1 = fmaf(xs[t][c+1], wr[c+1], a1);
                a2 = fmaf(xs[t][c+2], wr[c+2], a2);
                a3 = fmaf(xs[t][c+3], wr[c+3], a3);
            }
            a0 = fmaf(xs[t][52], wr[52], a0);
            pre[t][gate] = (a0 + a1) + (a2 + a3);
        }
    }
    __syncthreads();

    // ---- layer-0 recurrence (warp0=fwd, warp1=bwd, shfl) ----
    if (tid < 64) {
        const int dir = tid >> 5, u = tid & 31;
        float wi[HLc], wf[HLc], wg[HLc], wo[HLc];
        if (u < HLc) {
            #pragma unroll
            for (int c = 0; c < HLc; c++) {
                wi[c] = wh0sh[(dir*G4      + u)*HLc + c];
                wf[c] = wh0sh[(dir*G4 + 12 + u)*HLc + c];
                wg[c] = wh0sh[(dir*G4 + 24 + u)*HLc + c];
                wo[c] = wh0sh[(dir*G4 + 36 + u)*HLc + c];
            }
        } else {
            #pragma unroll
            for (int c = 0; c < HLc; c++) { wi[c]=wf[c]=wg[c]=wo[c]=0.f; }
        }
        float h = 0.f, cs = 0.f;
        for (int s = 0; s < TT; s++) {
            const int t = dir ? (TT - 1 - s) : s;
            float gi, gf, gg, go;
            if (u < HLc) {
                gi = pre[t][dir*G4      + u];
                gf = pre[t][dir*G4 + 12 + u];
                gg = pre[t][dir*G4 + 24 + u];
                go = pre[t][dir*G4 + 36 + u];
            } else { gi = gf = gg = go = 0.f; }
            #pragma unroll
            for (int c = 0; c < HLc; c++) {
                float hc = __shfl_sync(0xffffffffu, h, c);
                gi = fmaf(hc, wi[c], gi);
                gf = fmaf(hc, wf[c], gf);
                gg = fmaf(hc, wg[c], gg);
                go = fmaf(hc, wo[c], go);
            }
            cs = sigf(gf)*cs + sigf(gi)*tanh_fast(gg);
            h  = sigf(go)*tanh_fast(cs);
            if (u < HLc) hbuf[t][dir*HLc + u] = h;
        }
    }
    __syncthreads();

    // ---- layer-1 pregates ----
    {
        const int gate = tid % 96;
        const int tq   = tid / 96;
        float wr[2*HLc];
        #pragma unroll
        for (int c = 0; c < 2*HLc; c++) wr[c] = w1sh[gate*2*HLc + c];
        const float b = b1sh[gate];
        for (int t = tq*16; t < tq*16 + 16; t++) {
            float a0 = b, a1 = 0.f, a2 = 0.f, a3 = 0.f;
            #pragma unroll
            for (int c = 0; c < 2*HLc; c += 4) {
                a0 = fmaf(hbuf[t][c+0], wr[c+0], a0);
                a1 = fmaf(hbuf[t][c+1], wr[c+1], a1);
                a2 = fmaf(hbuf[t][c+2], wr[c+2], a2);
                a3 = fmaf(hbuf[t][c+3], wr[c+3], a3);
            }
            pre[t][gate] = (a0 + a1) + (a2 + a3);
        }
    }
    __syncthreads();

    // ---- layer-1 recurrence ----
    if (tid < 64) {
        const int dir = tid >> 5, u = tid & 31;
        float wi[HLc], wf[HLc], wg[HLc], wo[HLc];
        if (u < HLc) {
            #pragma unroll
            for (int c = 0; c < HLc; c++) {
                wi[c] = wh1sh[(dir*G4      + u)*HLc + c];
                wf[c] = wh1sh[(dir*G4 + 12 + u)*HLc + c];
                wg[c] = wh1sh[(dir*G4 + 24 + u)*HLc + c];
                wo[c] = wh1sh[(dir*G4 + 36 + u)*HLc + c];
            }
        } else {
            #pragma unroll
            for (int c = 0; c < HLc; c++) { wi[c]=wf[c]=wg[c]=wo[c]=0.f; }
        }
        float h = 0.f, cs = 0.f;
        for (int s = 0; s < TT; s++) {
            const int t = dir ? (TT - 1 - s) : s;
            float gi, gf, gg, go;
            if (u < HLc) {
                gi = pre[t][dir*G4      + u];
                gf = pre[t][dir*G4 + 12 + u];
                gg = pre[t][dir*G4 + 24 + u];
                go = pre[t][dir*G4 + 36 + u];
            } else { gi = gf = gg = go = 0.f; }
            #pragma unroll
            for (int c = 0; c < HLc; c++) {
                float hc = __shfl_sync(0xffffffffu, h, c);
                gi = fmaf(hc, wi[c], gi);
                gf = fmaf(hc, wf[c], gf);
                gg = fmaf(hc, wg[c], gg);
                go = fmaf(hc, wo[c], go);
            }
            cs = sigf(gf)*cs + sigf(gi)*tanh_fast(gg);
            h  = sigf(go)*tanh_fast(cs);
            if (u < HLc) hbuf[t][dir*HLc + u] = h;
        }
    }
    __syncthreads();

    // ---- fused QKV for layer 1 ----
    if (tid < 288) {
        const int oc = tid % 72;
        const int tq = tid / 72;
        float wr[NUc];
        #pragma unroll
        for (int c = 0; c < NUc; c++) wr[c] = wqsh[oc*NUc + c];
        const float b = bqsh[oc];
        const int e  = oc / NUc;
        const int ch = oc % NUc;
        const float scale = (e == 0) ? QSCALE : 1.0f;
        float* dst = (e == 0) ? g_q0 : (e == 1) ? g_k0 : g_v0;
        for (int t = tq*16; t < tq*16 + 16; t++) {
            float a0 = b, a1 = 0.f, a2 = 0.f, a3 = 0.f;
            #pragma unroll
            for (int c = 0; c < NUc; c += 4) {
                a0 = fmaf(hbuf[t][c+0], wr[c+0], a0);
                a1 = fmaf(hbuf[t][c+1], wr[c+1], a1);
                a2 = fmaf(hbuf[t][c+2], wr[c+2], a2);
                a3 = fmaf(hbuf[t][c+3], wr[c+3], a3);
            }
            dst[(t*WW + w)*NUc + ch] = ((a0 + a1) + (a2 + a3)) * scale;
        }
    }
}

// ---------------------------------------------------------------------------
// NATTEN-2D, query-in-register decomposition:
// 4x8 pixel tile, 256 threads (8 warps). warp = (head, row-pair); each warp
// runs 2 row-tasks; per task: lane = union column, K/V loaded ONCE per
// neighbor-row and reused for all 8 queries (held in registers).
// Unshifted softmax (logits bounded). mode0 -> QKV layer2, mode1 -> head.
// ---------------------------------------------------------------------------
__global__ void __launch_bounds__(256)
natten_kernel(const float* __restrict__ qsrc,
              const float* __restrict__ ksrc,
              const float* __restrict__ vsrc,
              const float* __restrict__ rpb,
              const float* __restrict__ pw,
              const float* __restrict__ pb,
              const float* __restrict__ qkv_w,
              const float* __restrict__ qkv_b,
              const float* __restrict__ ow,
              const float* __restrict__ ob,
              float* __restrict__ out,
              int mode)
{
    const int i0 = blockIdx.y * 4;
    const int j0 = blockIdx.x * 8;
    extern __shared__ float sm[];
    float* ks   = sm;                           // [28*32][PITCH]
    float* vs   = ks + UROWS*32*PITCH;
    float* rpsh = vs + UROWS*32*PITCH;          // [4][28][49]
    float* ao   = rpsh + 4*RPROWS*49;           // [32][24]
    float* po   = ao + 32*NUc;                  // [32][24]
    float* wsh  = po + 32*NUc;                  // [72*24]
    float* bsh  = wsh + 72*NUc;                 // [72]

    const int tid = threadIdx.x;

    const int si0 = min(max(i0     - 12, 0), TT - KK);
    const int si3 = min(max(i0 + 3 - 12, 0), TT - KK);
    const int nrows = si3 + KK - si0;                      // 25..28
    const int sj_min  = min(max(j0     - 12, 0), WW - KK);
    const int sj_last = min(max(j0 + 7 - 12, 0), WW - KK);
    const int ncols   = sj_last + KK - sj_min;             // <= 32
    const int rmin = si3 - (i0 + 3) + (KK - 1);

    if (mode == 0) {
        for (int x = tid; x < 72*NUc; x += 256) wsh[x] = qkv_w[x];
        if (tid < 72) bsh[tid] = qkv_b[tid];
    }

    // stage rpb rows rmin..rmin+27, all 49 cols (always in range)
    for (int idx = tid; idx < 4*RPROWS*49; idx += 256) {
        int hn = idx / (RPROWS*49);
        int rem = idx - hn*(RPROWS*49);
        int rr = rem / 49, cc = rem - rr*49;
        rpsh[idx] = __ldg(rpb + hn*2401 + (rmin + rr)*49 + cc);
    }

    // stage K/V: nrows x 32 columns (column-clamped to stay finite)
    const int npx = nrows * 32;
    for (int spx = tid; spx < npx; spx += 256) {
        int a = spx >> 5, c = spx & 31;
        int cc = min(c, ncols - 1);
        int gpx = (si0 + a)*WW + (sj_min + cc);
        float* kdst = ks + (a*32 + c)*PITCH;
        float* vdst = vs + (a*32 + c)*PITCH;
        const float4* kp = (const float4*)(ksrc + gpx*NUc);
        const float4* vp = (const float4*)(vsrc + gpx*NUc);
        #pragma unroll
        for (int f = 0; f < 6; f++) {
            float4 kd = kp[f];
            *(float2*)(kdst + f*4)     = make_float2(kd.x, kd.y);
            *(float2*)(kdst + f*4 + 2) = make_float2(kd.z, kd.w);
        }
        #pragma unroll
        for (int f = 0; f < 6; f++) {
            float4 vd = vp[f];
            *(float2*)(vdst + f*4)     = make_float2(vd.x, vd.y);
            *(float2*)(vdst + f*4 + 2) = make_float2(vd.z, vd.w);
        }
    }
    __syncthreads();

    const int warp = tid >> 5, lane = tid & 31;
    const int n  = warp & 3;            // head
    const int rp = warp >> 2;           // row-pair 0/1

    // per-query lane constants (row-independent)
    int   rjp[8];
    float vf [8];
    #pragma unroll
    for (int p = 0; p < 8; p++) {
        int sj = min(max(j0 + p - 12, 0), WW - KK);
        int cb = sj - sj_min;
        bool valid = ((unsigned)(lane - cb)) < 25u;
        int rj = (lane - cb) + (sj - (j0 + p) + (KK - 1));
        rjp[p] = min(max(rj, 0), 48);
        vf[p]  = valid ? 1.0f : 0.0f;
    }

    for (int tr = 0; tr < 2; tr++) {
        const int r = rp*2 + tr;
        const int i = i0 + r;
        const int sir = min(max(i - 12, 0), TT - KK);
        const int arow = sir - si0;                      // 0..3
        const int ra   = (sir - i + (KK - 1)) - rmin;    // 0..3
        const float* rpw = rpsh + n*(RPROWS*49) + ra*49;

        // 8 query vectors in registers
        float qv[48];
        #pragma unroll
        for (int p = 0; p < 8; p++) {
            const float2* qp = (const float2*)(qsrc + ((i*WW + j0 + p)*NUc + n*HDd));
            float2 a0 = qp[0], a1 = qp[1], a2 = qp[2];
            qv[p*6+0]=a0.x; qv[p*6+1]=a0.y;
            qv[p*6+2]=a1.x; qv[p*6+3]=a1.y;
            qv[p*6+4]=a2.x; qv[p*6+5]=a2.y;
        }

        float sum[8];
        float oa[48];
        #pragma unroll
        for (int p = 0; p < 8; p++) sum[p] = 0.f;
        #pragma unroll
        for (int x = 0; x < 48; x++) oa[x] = 0.f;

        #pragma unroll 1
        for (int a = 0; a < KK; a++) {
            const int base = ((arow + a)*32 + lane)*PITCH + n*HDd;
            const float* kp = ks + base;
            const float* vp = vs + base;
            float2 k01 = *(const float2*)(kp);
            float2 k23 = *(const float2*)(kp + 2);
            float2 k45 = *(const float2*)(kp + 4);
            float2 v01 = *(const float2*)(vp);
            float2 v23 = *(const float2*)(vp + 2);
            float2 v45 = *(const float2*)(vp + 4);
            const float* rpr = rpw + a*49;
            #pragma unroll
            for (int p = 0; p < 8; p++) {
                float lg = rpr[rjp[p]];
                lg = fmaf(qv[p*6+0], k01.x, lg);
                lg = fmaf(qv[p*6+1], k01.y, lg);
                lg = fmaf(qv[p*6+2], k23.x, lg);
                lg = fmaf(qv[p*6+3], k23.y, lg);
                lg = fmaf(qv[p*6+4], k45.x, lg);
                lg = fmaf(qv[p*6+5], k45.y, lg);
                float pr = __expf(lg) * vf[p];
                sum[p] += pr;
                oa[p*6+0] = fmaf(pr, v01.x, oa[p*6+0]);
                oa[p*6+1] = fmaf(pr, v01.y, oa[p*6+1]);
                oa[p*6+2] = fmaf(pr, v23.x, oa[p*6+2]);
                oa[p*6+3] = fmaf(pr, v23.y, oa[p*6+3]);
                oa[p*6+4] = fmaf(pr, v45.x, oa[p*6+4]);
                oa[p*6+5] = fmaf(pr, v45.y, oa[p*6+5]);
            }
        }

        // cross-lane (cross-column) reduction per query
        #pragma unroll
        for (int p = 0; p < 8; p++) {
            float s  = sum[p];
            float o0 = oa[p*6+0], o1 = oa[p*6+1], o2 = oa[p*6+2];
            float o3 = oa[p*6+3], o4 = oa[p*6+4], o5 = oa[p*6+5];
            #pragma unroll
            for (int off = 16; off > 0; off >>= 1) {
                s  += __shfl_xor_sync(0xffffffffu, s,  off);
                o0 += __shfl_xor_sync(0xffffffffu, o0, off);
                o1 += __shfl_xor_sync(0xffffffffu, o1, off);
                o2 += __shfl_xor_sync(0xffffffffu, o2, off);
                o3 += __shfl_xor_sync(0xffffffffu, o3, off);
                o4 += __shfl_xor_sync(0xffffffffu, o4, off);
                o5 += __shfl_xor_sync(0xffffffffu, o5, off);
            }
            if (lane == 0) {
                float inv = 1.0f / s;
                float* dst = ao + (r*8 + p)*NUc + n*HDd;
                dst[0]=o0*inv; dst[1]=o1*inv; dst[2]=o2*inv;
                dst[3]=o3*inv; dst[4]=o4*inv; dst[5]=o5*inv;
            }
        }
    }
    __syncthreads();

    // output projection (24x24) for 32 pixels
    for (int idx = tid; idx < 32*NUc; idx += 256) {
        int pp = idx / NUc, oc = idx % NUc;
        float acc = __ldg(pb + oc);
        const float* wrow = pw + oc*NUc;
        #pragma unroll
        for (int ic = 0; ic < NUc; ic++)
            acc = fmaf(ao[pp*NUc + ic], __ldg(wrow + ic), acc);
        po[pp*NUc + oc] = acc;
    }
    __syncthreads();

    if (mode == 0) {
        // fused QKV for layer 2: 32 px * 72 oc
        for (int idx = tid; idx < 32*72; idx += 256) {
            int pp = idx / 72, oc = idx % 72;
            float acc = bsh[oc];
            const float* wrow = wsh + oc*NUc;
            const float* xr = po + pp*NUc;
            #pragma unroll
            for (int c = 0; c < NUc; c++) acc = fmaf(xr[c], wrow[c], acc);
            int e = oc / NUc, ch = oc % NUc;
            int gpx = (i0 + (pp >> 3))*WW + j0 + (pp & 7);
            if      (e == 0) g_q1[gpx*NUc + ch] = acc * QSCALE;
            else if (e == 1) g_k1[gpx*NUc + ch] = acc;
            else             g_v1[gpx*NUc + ch] = acc;
        }
    } else {
        // final head (24 -> 5)
        if (tid < 32*5) {
            int pp = tid / 5, rr = tid % 5;
            float acc = __ldg(ob + rr);
            const float* wrow = ow + rr*NUc;
            #pragma unroll
            for (int ic = 0; ic < NUc; ic++)
                acc = fmaf(po[pp*NUc + ic], __ldg(wrow + ic), acc);
            out[((i0 + (pp >> 3))*WW + j0 + (pp & 7))*5 + rr] = acc;
        }
    }
}

// ---------------------------------------------------------------------------
extern "C" void kernel_launch(void* const* d_in, const int* in_sizes, int n_in,
                              void* d_out, int out_size)
{
    const float* features  = (const float*)d_in[0];
    const int*   condition = (const int*)  d_in[1];
    const float* mask      = (const float*)d_in[2];
    const float* emb       = (const float*)d_in[3];
    const float* wih0      = (const float*)d_in[4];
    const float* whh0      = (const float*)d_in[5];
    const float* bih0      = (const float*)d_in[6];
    const float* bhh0      = (const float*)d_in[7];
    const float* wih1      = (const float*)d_in[8];
    const float* whh1      = (const float*)d_in[9];
    const float* bih1      = (const float*)d_in[10];
    const float* bhh1      = (const float*)d_in[11];
    const float* qkv_w     = (const float*)d_in[12];
    const float* qkv_b     = (const float*)d_in[13];
    const float* rpb       = (const float*)d_in[14];
    const float* proj_w    = (const float*)d_in[15];
    const float* proj_b    = (const float*)d_in[16];
    const float* out_w     = (const float*)d_in[17];
    const float* out_b     = (const float*)d_in[18];
    float* out = (float*)d_out;

    float *pq0, *pk0, *pv0, *pq1, *pk1, *pv1;
    cudaGetSymbolAddress((void**)&pq0, g_q0);
    cudaGetSymbolAddress((void**)&pk0, g_k0);
    cudaGetSymbolAddress((void**)&pv0, g_v0);
    cudaGetSymbolAddress((void**)&pq1, g_q1);
    cudaGetSymbolAddress((void**)&pk1, g_k1);
    cudaGetSymbolAddress((void**)&pv1, g_v1);

    const int natten_smem =
        (2*UROWS*32*PITCH + 4*RPROWS*49 + 2*32*NUc + 72*NUc + 72)
        * (int)sizeof(float);   // 221,664 B
    cudaFuncSetAttribute(natten_kernel,
                         cudaFuncAttributeMaxDynamicSharedMemorySize, natten_smem);

    // 1) fused LSTM + QKV(layer1)
    lstm_kernel<<<WW, 384>>>(features, condition, mask, emb,
                             wih0, whh0, bih0, bhh0,
                             wih1, whh1, bih1, bhh1,
                             qkv_w, qkv_b);

    dim3 ngrid(WW/8, TT/4);   // 11 x 16 = 176 blocks

    // 2) NATTEN layer 1 (+ fused QKV for layer 2)
    natten_kernel<<<ngrid, 256, natten_smem>>>(pq0, pk0, pv0,
                                               rpb, proj_w, proj_b,
                                               qkv_w, qkv_b, out_w, out_b,
                                               nullptr, 0);

    // 3) NATTEN layer 2 (+ fused head) -> d_out
    natten_kernel<<<ngrid, 256, natten_smem>>>(pq1, pk1, pv1,
                                               rpb, proj_w, proj_b,
                                               qkv_w, qkv_b, out_w, out_b,
                                               out, 1);
}